// round 12
// baseline (speedup 1.0000x reference)
#include <cuda_runtime.h>

#define IW 512
#define H 256
#define OW 512
#define E 64
#define NA 2048
#define NAP 2560          // padded assignment capacity (8-aligned segments)
#define XP 2560           // column stride of dup arrays

typedef unsigned long long u64;

// ---------------- device scratch (no allocs allowed) ----------------
__device__ __align__(16) u64   g_xd[(size_t)IW * XP];  // 10.5 MB (x,x) dup [k][perm]
__device__ __align__(16) u64   g_vd[(size_t)H * XP];   //  5.2 MB (relu v, relu v) dup [h][perm]
__device__ __align__(16) float g_V[NAP * H];           //  2.6 MB pre-relu sums [perm][h]
__device__ __align__(16) float g_tmp2[NA / 2 * OW];    //  2.0 MB kz=1 output half
__device__ int   g_topk_idx[NA];
__device__ float g_topk_score[NA];
__device__ int   g_seg_start[E + 1];
__device__ int   g_seg_cnt[E];
__device__ int   g_perm_a[NAP];
__device__ float g_perm_score[NAP];

// ---------------- packed f32x2 helpers (sm_103a) ----------------
__device__ __forceinline__ u64 pack2(float a, float b) {
    u64 r; unsigned ai = __float_as_uint(a), bi = __float_as_uint(b);
    asm("mov.b64 %0, {%1, %2};" : "=l"(r) : "r"(ai), "r"(bi));
    return r;
}
__device__ __forceinline__ void ffma2(u64 &d, u64 a, u64 b) {
    asm("fma.rn.f32x2 %0, %1, %2, %0;" : "+l"(d) : "l"(a), "l"(b));
}
__device__ __forceinline__ float2 unpack2(u64 v) {
    unsigned lo, hi;
    asm("mov.b64 {%0, %1}, %2;" : "=r"(lo), "=r"(hi) : "l"(v));
    float2 f; f.x = __uint_as_float(lo); f.y = __uint_as_float(hi);
    return f;
}

// ---------------- zero kernels ----------------
__global__ __launch_bounds__(256) void zero_out_kernel(float4* __restrict__ out)
{
    int idx = blockIdx.x * 256 + threadIdx.x;   // 131072 f4
    out[idx] = make_float4(0.f, 0.f, 0.f, 0.f);
}
__global__ __launch_bounds__(256) void zero_scratch_kernel()
{
    int idx = blockIdx.x * 256 + threadIdx.x;   // 294912 f4 = 163840 + 131072
    float4 z = make_float4(0.f, 0.f, 0.f, 0.f);
    if (idx < 163840) ((float4*)g_V)[idx] = z;
    else              ((float4*)g_tmp2)[idx - 163840] = z;
}

// ---------------- kernel 1: routing ----------------
__global__ __launch_bounds__(256) void routing_kernel(
    const float* __restrict__ x, const float* __restrict__ noise,
    const float* __restrict__ mixer, const float* __restrict__ nctl)
{
    __shared__ __align__(16) u64 mns[32][64];
    __shared__ __align__(16) u64 xs2[8][32];
    __shared__ float hs[8][64];
    int tid = threadIdx.x;
    int t0 = blockIdx.x * 8;
    int ee = tid & 63, tg = tid >> 6;

    u64 acc2[2] = {0ull, 0ull};

    for (int i0 = 0; i0 < IW; i0 += 32) {
#pragma unroll
        for (int q = 0; q < 8; q++) {
            int id = tid + 256 * q; int ii = id >> 6, e2 = id & 63;
            mns[ii][e2] = pack2(mixer[(i0 + ii) * E + e2], nctl[(i0 + ii) * E + e2]);
        }
        {
            int tt = tid >> 5, ii = tid & 31;
            if (tt < 8) {
                float v = x[(t0 + tt) * IW + i0 + ii];
                xs2[tt][ii] = pack2(v, v);
            }
        }
        __syncthreads();
#pragma unroll 8
        for (int ii = 0; ii < 32; ii++) {
            u64 mn = mns[ii][ee];
            ffma2(acc2[0], xs2[tg * 2 + 0][ii], mn);
            ffma2(acc2[1], xs2[tg * 2 + 1][ii], mn);
        }
        __syncthreads();
    }

#pragma unroll
    for (int j = 0; j < 2; j++) {
        int t = tg * 2 + j;
        float2 a = unpack2(acc2[j]);
        float z = a.y;
        float sp = (z > 20.f) ? z : log1pf(expf(z));
        hs[t][ee] = a.x + noise[(t0 + t) * E + ee] * sp;
    }
    __syncthreads();

    if (tid < 8) {
        int t = tid;
        float v0 = -1e30f, v1 = -1e30f; int i0 = -1, i1 = -1;
        for (int ec = 0; ec < 64; ec++) {
            float v = hs[t][ec];
            if (v > v0)      { v1 = v0; i1 = i0; v0 = v; i0 = ec; }
            else if (v > v1) { v1 = v; i1 = ec; }
        }
        float e1 = expf(v1 - v0);
        float s0 = 1.f / (1.f + e1);
        float s1 = e1 * s0;
        g_topk_idx[(t0 + t) * 2 + 0] = i0;
        g_topk_idx[(t0 + t) * 2 + 1] = i1;
        g_topk_score[(t0 + t) * 2 + 0] = s0;
        g_topk_score[(t0 + t) * 2 + 1] = s1;
    }
}

// ---------------- kernel 2: group (8-aligned segment starts + pad fill) ----------------
__global__ __launch_bounds__(256) void group_kernel()
{
    __shared__ int cnt[E];
    __shared__ int st[E + 1];
    __shared__ int cur[E];
    int tid = threadIdx.x;
    if (tid < E) cnt[tid] = 0;
    __syncthreads();
    for (int a = tid; a < NA; a += 256) atomicAdd(&cnt[g_topk_idx[a]], 1);
    __syncthreads();
    if (tid == 0) {
        int run = 0;
        for (int e2 = 0; e2 < E; e2++) {
            st[e2] = run;
            run = (run + cnt[e2] + 7) & ~7;   // pad each segment end to 8
        }
        st[E] = run;
    }
    __syncthreads();
    if (tid < E) { cur[tid] = st[tid]; g_seg_cnt[tid] = cnt[tid]; }
    if (tid <= E) g_seg_start[tid] = st[tid];
    __syncthreads();
    for (int a = tid; a < NA; a += 256) {
        int e2 = g_topk_idx[a];
        int pos = atomicAdd(&cur[e2], 1);
        g_perm_a[pos] = a;
        g_perm_score[pos] = g_topk_score[a];
    }
    __syncthreads();
    // fill intra-segment pad slots
    if (tid < E) {
        for (int p = st[tid] + cnt[tid]; p < st[tid + 1]; p++) {
            g_perm_a[p] = 0; g_perm_score[p] = 0.f;
        }
    }
    // fill tail up to capacity
    for (int p = st[E] + tid; p < NAP; p += 256) {
        g_perm_a[p] = 0; g_perm_score[p] = 0.f;
    }
}

// ---------------- kernel 3: x transpose-dup: g_xd[k][p] = (x,x) ----------------
__global__ __launch_bounds__(128) void xdup_kernel(const float* __restrict__ x)
{
    __shared__ float sm[32][33];
    int p0 = (blockIdx.x >> 4) * 32;    // 80 p-tiles
    int k0 = (blockIdx.x & 15) * 32;    // 16 k-tiles
    int tid = threadIdx.x;
#pragma unroll
    for (int q = 0; q < 8; q++) {
        int id = tid + 128 * q; int pp = id >> 5, ii = id & 31;
        int tk = g_perm_a[p0 + pp] >> 1;
        sm[pp][ii] = x[tk * IW + k0 + ii];
    }
    __syncthreads();
#pragma unroll
    for (int q = 0; q < 8; q++) {
        int id = tid + 128 * q; int kk = id >> 5, pp = id & 31;
        float v = sm[pp][kk];
        g_xd[(size_t)(k0 + kk) * XP + p0 + pp] = pack2(v, v);
    }
}

// ---------------- kernel 5: V relu + transpose-dup: g_vd[h][p] = (r,r) ----------------
__global__ __launch_bounds__(128) void vdup_kernel()
{
    __shared__ float sm[32][33];
    int p0 = (blockIdx.x >> 3) * 32;    // 80 p-tiles
    int h0 = (blockIdx.x & 7) * 32;     // 8 h-tiles
    int tid = threadIdx.x;
#pragma unroll
    for (int q = 0; q < 8; q++) {
        int id = tid + 128 * q; int pp = id >> 5, ii = id & 31;
        sm[pp][ii] = g_V[(size_t)(p0 + pp) * H + h0 + ii];
    }
    __syncthreads();
#pragma unroll
    for (int q = 0; q < 8; q++) {
        int id = tid + 128 * q; int kk = id >> 5, pp = id & 31;
        float v = fmaxf(sm[pp][kk], 0.f);
        g_vd[(size_t)(h0 + kk) * XP + p0 + pp] = pack2(v, v);
    }
}

// ---------------- kernel 4: ffn1 split-K: g_V += X_e @ W1_e (+ b1 on kz=0) --------
// grid (2 hc, 64 e, 8 z = 4 chunk x 2 ksplit), 128 thr.
// warp = 8 tok x 128 h (4 h/lane). x via broadcast LDG.128 of g_xd. smem = W only.
__global__ __launch_bounds__(128, 4) void ffn1_kernel(
    const float* __restrict__ w1s, const float* __restrict__ b1s)
{
    __shared__ __align__(16) float ws[32][132];
    int e = blockIdx.y, hc = blockIdx.x, z = blockIdx.z;
    int kz = z & 1, cs = z >> 1;
    int kbase = kz * 256;
    int s = g_seg_start[e];
    int cnt = g_seg_cnt[e];
    int tid = threadIdx.x, w = tid >> 5, l = tid & 31;
    const float* wbase = w1s + ((size_t)e * IW + kbase) * H + hc * 128;

    int wr[8], wc[8];
#pragma unroll
    for (int q = 0; q < 8; q++) {
        int f4 = tid + 128 * q;
        wr[q] = f4 >> 5; wc[q] = (f4 & 31) * 4;
    }

    for (int c0 = cs * 32; c0 < cnt; c0 += 128) {
        int nt = min(32, cnt - c0);
        const u64* xcol = g_xd + (size_t)kbase * XP + (s + c0 + w * 8);

        float4 pw[8];
#pragma unroll
        for (int q = 0; q < 8; q++)
            pw[q] = *(const float4*)(wbase + (size_t)wr[q] * H + wc[q]);

        u64 acc[8][2];
        if (kz == 0) {
            float4 bv = *(const float4*)(b1s + e * H + hc * 128 + l * 4);
#pragma unroll
            for (int j = 0; j < 8; j++) {
                acc[j][0] = pack2(bv.x, bv.y);
                acc[j][1] = pack2(bv.z, bv.w);
            }
        } else {
#pragma unroll
            for (int j = 0; j < 8; j++) { acc[j][0] = 0ull; acc[j][1] = 0ull; }
        }

        for (int i0 = 0; i0 < 256; i0 += 32) {
            __syncthreads();
#pragma unroll
            for (int q = 0; q < 8; q++)
                *(float4*)&ws[wr[q]][wc[q]] = pw[q];
            __syncthreads();
            if (i0 + 32 < 256) {
                const float* wb = wbase + (size_t)(i0 + 32) * H;
#pragma unroll
                for (int q = 0; q < 8; q++)
                    pw[q] = *(const float4*)(wb + (size_t)wr[q] * H + wc[q]);
            }
            const u64* xr = xcol + (size_t)i0 * XP;
#pragma unroll 8
            for (int kk = 0; kk < 32; kk++) {
                ulonglong2 wl = *(ulonglong2*)&ws[kk][l * 4];
                ulonglong2 xa = *(const ulonglong2*)(xr + 0);
                ulonglong2 xb = *(const ulonglong2*)(xr + 2);
                ulonglong2 xc = *(const ulonglong2*)(xr + 4);
                ulonglong2 xd2 = *(const ulonglong2*)(xr + 6);
                ffma2(acc[0][0], xa.x, wl.x); ffma2(acc[0][1], xa.x, wl.y);
                ffma2(acc[1][0], xa.y, wl.x); ffma2(acc[1][1], xa.y, wl.y);
                ffma2(acc[2][0], xb.x, wl.x); ffma2(acc[2][1], xb.x, wl.y);
                ffma2(acc[3][0], xb.y, wl.x); ffma2(acc[3][1], xb.y, wl.y);
                ffma2(acc[4][0], xc.x, wl.x); ffma2(acc[4][1], xc.x, wl.y);
                ffma2(acc[5][0], xc.y, wl.x); ffma2(acc[5][1], xc.y, wl.y);
                ffma2(acc[6][0], xd2.x, wl.x); ffma2(acc[6][1], xd2.x, wl.y);
                ffma2(acc[7][0], xd2.y, wl.x); ffma2(acc[7][1], xd2.y, wl.y);
                xr += XP;
            }
        }

#pragma unroll
        for (int j = 0; j < 8; j++) {
            int t = w * 8 + j;
            if (t < nt) {
                float2 f0 = unpack2(acc[j][0]), f1 = unpack2(acc[j][1]);
                float* dst = g_V + (size_t)(s + c0 + t) * H + hc * 128 + l * 4;
                atomicAdd(dst + 0, f0.x);
                atomicAdd(dst + 1, f0.y);
                atomicAdd(dst + 2, f1.x);
                atomicAdd(dst + 3, f1.y);
            }
        }
    }
}

// ---------------- kernel 6: ffn2 split-K: {out|g_tmp2} += sc*(relu(V)@W2 (+b2)) --
// grid (4 oc, 64 e, 8 z = 4 chunk x 2 ksplit), 128 thr.
// warp = 8 tok x 128 o. V via broadcast LDG.128 of g_vd (relu pre-applied).
__global__ __launch_bounds__(128, 4) void ffn2_kernel(
    const float* __restrict__ w2s, const float* __restrict__ b2s,
    float* __restrict__ out)
{
    __shared__ __align__(16) float ws2[32][132];
    int e = blockIdx.y, oc = blockIdx.x, z = blockIdx.z;
    int kz = z & 1, cs = z >> 1;
    int hbase = kz * 128;
    int s = g_seg_start[e];
    int cnt = g_seg_cnt[e];
    int tid = threadIdx.x, w = tid >> 5, l = tid & 31;
    const float* wbase = w2s + ((size_t)e * H + hbase) * OW + oc * 128;
    float* tgt = (kz == 0) ? out : g_tmp2;

    int wr[8], wc[8];
#pragma unroll
    for (int q = 0; q < 8; q++) {
        int f4 = tid + 128 * q;
        wr[q] = f4 >> 5; wc[q] = (f4 & 31) * 4;
    }

    for (int c0 = cs * 32; c0 < cnt; c0 += 128) {
        int nt = min(32, cnt - c0);
        const u64* vcol = g_vd + (size_t)hbase * XP + (s + c0 + w * 8);

        float4 pw[8];
#pragma unroll
        for (int q = 0; q < 8; q++)
            pw[q] = *(const float4*)(wbase + (size_t)wr[q] * OW + wc[q]);

        u64 acc[8][2];
        if (kz == 0) {
            float4 bv = *(const float4*)(b2s + e * OW + oc * 128 + l * 4);
#pragma unroll
            for (int j = 0; j < 8; j++) {
                acc[j][0] = pack2(bv.x, bv.y);
                acc[j][1] = pack2(bv.z, bv.w);
            }
        } else {
#pragma unroll
            for (int j = 0; j < 8; j++) { acc[j][0] = 0ull; acc[j][1] = 0ull; }
        }

        for (int h0 = 0; h0 < 128; h0 += 32) {
            __syncthreads();
#pragma unroll
            for (int q = 0; q < 8; q++)
                *(float4*)&ws2[wr[q]][wc[q]] = pw[q];
            __syncthreads();
            if (h0 + 32 < 128) {
                const float* wb = wbase + (size_t)(h0 + 32) * OW;
#pragma unroll
                for (int q = 0; q < 8; q++)
                    pw[q] = *(const float4*)(wb + (size_t)wr[q] * OW + wc[q]);
            }
            const u64* vr = vcol + (size_t)h0 * XP;
#pragma unroll 8
            for (int kk = 0; kk < 32; kk++) {
                ulonglong2 wl = *(ulonglong2*)&ws2[kk][l * 4];
                ulonglong2 va = *(const ulonglong2*)(vr + 0);
                ulonglong2 vb = *(const ulonglong2*)(vr + 2);
                ulonglong2 vc = *(const ulonglong2*)(vr + 4);
                ulonglong2 vdd = *(const ulonglong2*)(vr + 6);
                ffma2(acc[0][0], va.x, wl.x); ffma2(acc[0][1], va.x, wl.y);
                ffma2(acc[1][0], va.y, wl.x); ffma2(acc[1][1], va.y, wl.y);
                ffma2(acc[2][0], vb.x, wl.x); ffma2(acc[2][1], vb.x, wl.y);
                ffma2(acc[3][0], vb.y, wl.x); ffma2(acc[3][1], vb.y, wl.y);
                ffma2(acc[4][0], vc.x, wl.x); ffma2(acc[4][1], vc.x, wl.y);
                ffma2(acc[5][0], vc.y, wl.x); ffma2(acc[5][1], vc.y, wl.y);
                ffma2(acc[6][0], vdd.x, wl.x); ffma2(acc[6][1], vdd.x, wl.y);
                ffma2(acc[7][0], vdd.y, wl.x); ffma2(acc[7][1], vdd.y, wl.y);
                vr += XP;
            }
        }

#pragma unroll
        for (int j = 0; j < 8; j++) {
            int t = w * 8 + j;
            if (t < nt) {
                int   a  = g_perm_a[s + c0 + t];
                float sc = g_perm_score[s + c0 + t];
                int   tk = a >> 1;
                float* dst = tgt + (size_t)tk * OW + oc * 128 + l * 4;
                float2 f0 = unpack2(acc[j][0]), f1 = unpack2(acc[j][1]);
                atomicAdd(dst + 0, sc * f0.x);
                atomicAdd(dst + 1, sc * f0.y);
                atomicAdd(dst + 2, sc * f1.x);
                atomicAdd(dst + 3, sc * f1.y);
            }
        }
    }
}

// ---------------- kernel 7: out += g_tmp2 (fixed order -> deterministic) --------
__global__ __launch_bounds__(256) void combine_kernel(float4* __restrict__ out)
{
    int idx = blockIdx.x * 256 + threadIdx.x;   // 131072 f4
    float4 a = out[idx];
    float4 b = ((const float4*)g_tmp2)[idx];
    out[idx] = make_float4(a.x + b.x, a.y + b.y, a.z + b.z, a.w + b.w);
}

// ---------------- launcher ----------------
extern "C" void kernel_launch(void* const* d_in, const int* in_sizes, int n_in,
                              void* d_out, int out_size)
{
    const float* x     = (const float*)d_in[0];
    const float* noise = (const float*)d_in[1];
    const float* w1s   = (const float*)d_in[2];
    const float* b1s   = (const float*)d_in[3];
    const float* w2s   = (const float*)d_in[4];
    const float* b2s   = (const float*)d_in[5];
    const float* mixer = (const float*)d_in[6];
    const float* nctl  = (const float*)d_in[7];

    zero_out_kernel<<<512, 256>>>((float4*)d_out);
    zero_scratch_kernel<<<1152, 256>>>();
    routing_kernel<<<128, 256>>>(x, noise, mixer, nctl);
    group_kernel<<<1, 256>>>();
    xdup_kernel<<<1280, 128>>>(x);
    ffn1_kernel<<<dim3(2, 64, 8), 128>>>(w1s, b1s);
    vdup_kernel<<<640, 128>>>();
    ffn2_kernel<<<dim3(4, 64, 8), 128>>>(w2s, b2s, (float*)d_out);
    combine_kernel<<<512, 256>>>((float4*)d_out);
}

// round 13
// speedup vs baseline: 1.0159x; 1.0159x over previous
#include <cuda_runtime.h>

#define IW 512
#define H 256
#define OW 512
#define E 64
#define NA 2048
#define NAP 2560          // padded assignment capacity (8-aligned segments)
#define XP 2560           // column stride of dup arrays
#define CH 16             // token chunk per worklist entry
#define MAXWL 256

typedef unsigned long long u64;

// ---------------- device scratch (no allocs allowed) ----------------
__device__ __align__(16) u64   g_xd[(size_t)IW * XP];  // 10.5 MB (x,x) dup [k][perm]
__device__ __align__(16) u64   g_vd[(size_t)H * XP];   //  5.2 MB (relu v, relu v) dup [h][perm]
__device__ int   g_topk_idx[NA];
__device__ float g_topk_score[NA];
__device__ int   g_seg_start[E + 1];
__device__ int   g_seg_cnt[E];
__device__ int   g_perm_a[NAP];
__device__ float g_perm_score[NAP];
__device__ int   g_wl[MAXWL];      // (expert<<16) | chunk_start
__device__ int   g_wl_n;

// ---------------- packed f32x2 helpers (sm_103a) ----------------
__device__ __forceinline__ u64 pack2(float a, float b) {
    u64 r; unsigned ai = __float_as_uint(a), bi = __float_as_uint(b);
    asm("mov.b64 %0, {%1, %2};" : "=l"(r) : "r"(ai), "r"(bi));
    return r;
}
__device__ __forceinline__ void ffma2(u64 &d, u64 a, u64 b) {
    asm("fma.rn.f32x2 %0, %1, %2, %0;" : "+l"(d) : "l"(a), "l"(b));
}
__device__ __forceinline__ float2 unpack2(u64 v) {
    unsigned lo, hi;
    asm("mov.b64 {%0, %1}, %2;" : "=r"(lo), "=r"(hi) : "l"(v));
    float2 f; f.x = __uint_as_float(lo); f.y = __uint_as_float(hi);
    return f;
}

// ---------------- kernel 1: routing (+ fused d_out zeroing) ----------------
__global__ __launch_bounds__(256) void routing_kernel(
    const float* __restrict__ x, const float* __restrict__ noise,
    const float* __restrict__ mixer, const float* __restrict__ nctl,
    float4* __restrict__ out)
{
    __shared__ __align__(16) u64 mns[32][64];
    __shared__ __align__(16) u64 xs2[8][32];
    __shared__ float hs[8][64];
    int tid = threadIdx.x;
    int t0 = blockIdx.x * 8;
    int ee = tid & 63, tg = tid >> 6;

    // fused zero of d_out: 131072 float4 over 32768 threads
    {
        int base = blockIdx.x * 256 + tid;
        float4 z = make_float4(0.f, 0.f, 0.f, 0.f);
#pragma unroll
        for (int q = 0; q < 4; q++) out[base + q * 32768] = z;
    }

    u64 acc2[2] = {0ull, 0ull};

    for (int i0 = 0; i0 < IW; i0 += 32) {
#pragma unroll
        for (int q = 0; q < 8; q++) {
            int id = tid + 256 * q; int ii = id >> 6, e2 = id & 63;
            mns[ii][e2] = pack2(mixer[(i0 + ii) * E + e2], nctl[(i0 + ii) * E + e2]);
        }
        {
            int tt = tid >> 5, ii = tid & 31;
            if (tt < 8) {
                float v = x[(t0 + tt) * IW + i0 + ii];
                xs2[tt][ii] = pack2(v, v);
            }
        }
        __syncthreads();
#pragma unroll 8
        for (int ii = 0; ii < 32; ii++) {
            u64 mn = mns[ii][ee];
            ffma2(acc2[0], xs2[tg * 2 + 0][ii], mn);
            ffma2(acc2[1], xs2[tg * 2 + 1][ii], mn);
        }
        __syncthreads();
    }

#pragma unroll
    for (int j = 0; j < 2; j++) {
        int t = tg * 2 + j;
        float2 a = unpack2(acc2[j]);
        float z = a.y;
        float sp = (z > 20.f) ? z : log1pf(expf(z));
        hs[t][ee] = a.x + noise[(t0 + t) * E + ee] * sp;
    }
    __syncthreads();

    if (tid < 8) {
        int t = tid;
        float v0 = -1e30f, v1 = -1e30f; int i0 = -1, i1 = -1;
        for (int ec = 0; ec < 64; ec++) {
            float v = hs[t][ec];
            if (v > v0)      { v1 = v0; i1 = i0; v0 = v; i0 = ec; }
            else if (v > v1) { v1 = v; i1 = ec; }
        }
        float e1 = expf(v1 - v0);
        float s0 = 1.f / (1.f + e1);
        float s1 = e1 * s0;
        g_topk_idx[(t0 + t) * 2 + 0] = i0;
        g_topk_idx[(t0 + t) * 2 + 1] = i1;
        g_topk_score[(t0 + t) * 2 + 0] = s0;
        g_topk_score[(t0 + t) * 2 + 1] = s1;
    }
}

// ---------------- kernel 2: group + deterministic worklist ----------------
__global__ __launch_bounds__(256) void group_kernel()
{
    __shared__ int cnt[E];
    __shared__ int st[E + 1];
    __shared__ int cur[E];
    __shared__ int wo[E];
    int tid = threadIdx.x;
    if (tid < E) cnt[tid] = 0;
    __syncthreads();
    for (int a = tid; a < NA; a += 256) atomicAdd(&cnt[g_topk_idx[a]], 1);
    __syncthreads();
    if (tid == 0) {
        int run = 0, wrun = 0;
        for (int e2 = 0; e2 < E; e2++) {
            st[e2] = run;
            run = (run + cnt[e2] + 7) & ~7;      // 8-aligned segment starts
            wo[e2] = wrun;
            wrun += (cnt[e2] + CH - 1) / CH;
        }
        st[E] = run;
        g_wl_n = wrun;
    }
    __syncthreads();
    if (tid < E) { cur[tid] = st[tid]; g_seg_cnt[tid] = cnt[tid]; }
    if (tid <= E) g_seg_start[tid] = st[tid];
    __syncthreads();
    for (int a = tid; a < NA; a += 256) {
        int e2 = g_topk_idx[a];
        int pos = atomicAdd(&cur[e2], 1);
        g_perm_a[pos] = a;
        g_perm_score[pos] = g_topk_score[a];
    }
    __syncthreads();
    if (tid < E) {
        // intra-segment pad fill
        for (int p = st[tid] + cnt[tid]; p < st[tid + 1]; p++) {
            g_perm_a[p] = 0; g_perm_score[p] = 0.f;
        }
        // worklist entries for this expert
        for (int c = 0; c * CH < cnt[tid]; c++)
            g_wl[wo[tid] + c] = (tid << 16) | (c * CH);
    }
    for (int p = st[E] + tid; p < NAP; p += 256) {
        g_perm_a[p] = 0; g_perm_score[p] = 0.f;
    }
}

// ---------------- kernel 3: x transpose-dup: g_xd[k][p] = (x,x) ----------------
__global__ __launch_bounds__(128) void xdup_kernel(const float* __restrict__ x)
{
    __shared__ float sm[32][33];
    int p0 = (blockIdx.x >> 4) * 32;    // 80 p-tiles
    int k0 = (blockIdx.x & 15) * 32;    // 16 k-tiles
    int tid = threadIdx.x;
#pragma unroll
    for (int q = 0; q < 8; q++) {
        int id = tid + 128 * q; int pp = id >> 5, ii = id & 31;
        int tk = g_perm_a[p0 + pp] >> 1;
        sm[pp][ii] = x[tk * IW + k0 + ii];
    }
    __syncthreads();
#pragma unroll
    for (int q = 0; q < 8; q++) {
        int id = tid + 128 * q; int kk = id >> 5, pp = id & 31;
        float v = sm[pp][kk];
        g_xd[(size_t)(k0 + kk) * XP + p0 + pp] = pack2(v, v);
    }
}

// ---------------- kernel 4: ffn1 -> writes relu'd dup transpose g_vd --------
// grid (MAXWL, 2 hc), 128 thr. Warp = 4 tok x 128 h (4 h/lane).
// per kk: 1 LDS.128 (W) + 2 broadcast LDG.128 (x-dup) + 8 FFMA2.
__global__ __launch_bounds__(128) void ffn1_kernel(
    const float* __restrict__ w1s, const float* __restrict__ b1s)
{
    __shared__ __align__(16) float ws[32][132];
    int bx = blockIdx.x;
    if (bx >= g_wl_n) return;
    int ent = g_wl[bx];
    int e = ent >> 16, c0 = ent & 0xffff;
    int hc = blockIdx.y;
    int s = g_seg_start[e];
    int nt = min(CH, g_seg_cnt[e] - c0);
    int tid = threadIdx.x, w = tid >> 5, l = tid & 31;
    const float* wbase = w1s + (size_t)e * IW * H + hc * 128;

    int wr[8], wc[8];
#pragma unroll
    for (int q = 0; q < 8; q++) {
        int f4 = tid + 128 * q;
        wr[q] = f4 >> 5; wc[q] = (f4 & 31) * 4;
    }

    int pbase = s + c0 + w * 4;
    const u64* xcol = g_xd + pbase;

    float4 pw[8];
#pragma unroll
    for (int q = 0; q < 8; q++)
        pw[q] = *(const float4*)(wbase + (size_t)wr[q] * H + wc[q]);

    u64 acc[4][2];
    float4 bv = *(const float4*)(b1s + e * H + hc * 128 + l * 4);
#pragma unroll
    for (int j = 0; j < 4; j++) {
        acc[j][0] = pack2(bv.x, bv.y);
        acc[j][1] = pack2(bv.z, bv.w);
    }

    for (int i0 = 0; i0 < IW; i0 += 32) {
        __syncthreads();
#pragma unroll
        for (int q = 0; q < 8; q++)
            *(float4*)&ws[wr[q]][wc[q]] = pw[q];
        __syncthreads();
        if (i0 + 32 < IW) {
            const float* wb = wbase + (size_t)(i0 + 32) * H;
#pragma unroll
            for (int q = 0; q < 8; q++)
                pw[q] = *(const float4*)(wb + (size_t)wr[q] * H + wc[q]);
        }
        const u64* xr = xcol + (size_t)i0 * XP;
#pragma unroll 8
        for (int kk = 0; kk < 32; kk++) {
            ulonglong2 wl2 = *(ulonglong2*)&ws[kk][l * 4];
            ulonglong2 xa = *(const ulonglong2*)(xr);
            ulonglong2 xb = *(const ulonglong2*)(xr + 2);
            ffma2(acc[0][0], xa.x, wl2.x); ffma2(acc[0][1], xa.x, wl2.y);
            ffma2(acc[1][0], xa.y, wl2.x); ffma2(acc[1][1], xa.y, wl2.y);
            ffma2(acc[2][0], xb.x, wl2.x); ffma2(acc[2][1], xb.x, wl2.y);
            ffma2(acc[3][0], xb.y, wl2.x); ffma2(acc[3][1], xb.y, wl2.y);
            xr += XP;
        }
    }

    // epilogue: relu + transposed dup write g_vd[h][perm]
    float r[4][4];
#pragma unroll
    for (int j = 0; j < 4; j++) {
        float2 f0 = unpack2(acc[j][0]), f1 = unpack2(acc[j][1]);
        r[j][0] = fmaxf(f0.x, 0.f); r[j][1] = fmaxf(f0.y, 0.f);
        r[j][2] = fmaxf(f1.x, 0.f); r[j][3] = fmaxf(f1.y, 0.f);
    }
    int hbase = hc * 128 + l * 4;
    int rem = nt - w * 4;                        // valid tokens in this warp
    if (rem >= 4) {
#pragma unroll
        for (int hh = 0; hh < 4; hh++) {
            u64* dst = g_vd + (size_t)(hbase + hh) * XP + pbase;
            ulonglong2 v0, v1;
            v0.x = pack2(r[0][hh], r[0][hh]); v0.y = pack2(r[1][hh], r[1][hh]);
            v1.x = pack2(r[2][hh], r[2][hh]); v1.y = pack2(r[3][hh], r[3][hh]);
            *(ulonglong2*)dst = v0;
            *(ulonglong2*)(dst + 2) = v1;
        }
    } else if (rem > 0) {
        for (int j = 0; j < rem; j++)
#pragma unroll
            for (int hh = 0; hh < 4; hh++)
                g_vd[(size_t)(hbase + hh) * XP + pbase + j] = pack2(r[j][hh], r[j][hh]);
    }
}

// ---------------- kernel 5: ffn2: out += score * (relu(V) @ W2 + b2) --------
// grid (MAXWL, 4 oc), 128 thr. Warp = 4 tok x 128 o. Atomic epilogue
// (exactly 2 commutative fp adds per out element -> deterministic).
__global__ __launch_bounds__(128) void ffn2_kernel(
    const float* __restrict__ w2s, const float* __restrict__ b2s,
    float* __restrict__ out)
{
    __shared__ __align__(16) float ws2[32][132];
    int bx = blockIdx.x;
    if (bx >= g_wl_n) return;
    int ent = g_wl[bx];
    int e = ent >> 16, c0 = ent & 0xffff;
    int oc = blockIdx.y;
    int s = g_seg_start[e];
    int nt = min(CH, g_seg_cnt[e] - c0);
    int tid = threadIdx.x, w = tid >> 5, l = tid & 31;
    const float* wbase = w2s + (size_t)e * H * OW + oc * 128;

    int wr[8], wc[8];
#pragma unroll
    for (int q = 0; q < 8; q++) {
        int f4 = tid + 128 * q;
        wr[q] = f4 >> 5; wc[q] = (f4 & 31) * 4;
    }

    int pbase = s + c0 + w * 4;
    const u64* vcol = g_vd + pbase;

    float4 pw[8];
#pragma unroll
    for (int q = 0; q < 8; q++)
        pw[q] = *(const float4*)(wbase + (size_t)wr[q] * OW + wc[q]);

    u64 acc[4][2];
    float4 bv = *(const float4*)(b2s + e * OW + oc * 128 + l * 4);
#pragma unroll
    for (int j = 0; j < 4; j++) {
        acc[j][0] = pack2(bv.x, bv.y);
        acc[j][1] = pack2(bv.z, bv.w);
    }

    for (int h0 = 0; h0 < H; h0 += 32) {
        __syncthreads();
#pragma unroll
        for (int q = 0; q < 8; q++)
            *(float4*)&ws2[wr[q]][wc[q]] = pw[q];
        __syncthreads();
        if (h0 + 32 < H) {
            const float* wb = wbase + (size_t)(h0 + 32) * OW;
#pragma unroll
            for (int q = 0; q < 8; q++)
                pw[q] = *(const float4*)(wb + (size_t)wr[q] * OW + wc[q]);
        }
        const u64* vr = vcol + (size_t)h0 * XP;
#pragma unroll 8
        for (int kk = 0; kk < 32; kk++) {
            ulonglong2 wl2 = *(ulonglong2*)&ws2[kk][l * 4];
            ulonglong2 va = *(const ulonglong2*)(vr);
            ulonglong2 vb = *(const ulonglong2*)(vr + 2);
            ffma2(acc[0][0], va.x, wl2.x); ffma2(acc[0][1], va.x, wl2.y);
            ffma2(acc[1][0], va.y, wl2.x); ffma2(acc[1][1], va.y, wl2.y);
            ffma2(acc[2][0], vb.x, wl2.x); ffma2(acc[2][1], vb.x, wl2.y);
            ffma2(acc[3][0], vb.y, wl2.x); ffma2(acc[3][1], vb.y, wl2.y);
            vr += XP;
        }
    }

#pragma unroll
    for (int j = 0; j < 4; j++) {
        int t = w * 4 + j;
        if (t < nt) {
            int   a  = g_perm_a[s + c0 + t];
            float sc = g_perm_score[s + c0 + t];
            int   tk = a >> 1;
            float* dst = out + (size_t)tk * OW + oc * 128 + l * 4;
            float2 f0 = unpack2(acc[j][0]), f1 = unpack2(acc[j][1]);
            atomicAdd(dst + 0, sc * f0.x);
            atomicAdd(dst + 1, sc * f0.y);
            atomicAdd(dst + 2, sc * f1.x);
            atomicAdd(dst + 3, sc * f1.y);
        }
    }
}

// ---------------- launcher ----------------
extern "C" void kernel_launch(void* const* d_in, const int* in_sizes, int n_in,
                              void* d_out, int out_size)
{
    const float* x     = (const float*)d_in[0];
    const float* noise = (const float*)d_in[1];
    const float* w1s   = (const float*)d_in[2];
    const float* b1s   = (const float*)d_in[3];
    const float* w2s   = (const float*)d_in[4];
    const float* b2s   = (const float*)d_in[5];
    const float* mixer = (const float*)d_in[6];
    const float* nctl  = (const float*)d_in[7];

    routing_kernel<<<128, 256>>>(x, noise, mixer, nctl, (float4*)d_out);
    group_kernel<<<1, 256>>>();
    xdup_kernel<<<1280, 128>>>(x);
    ffn1_kernel<<<dim3(MAXWL, 2), 128>>>(w1s, b1s);
    ffn2_kernel<<<dim3(MAXWL, 4), 128>>>(w2s, b2s, (float*)d_out);
}

// round 14
// speedup vs baseline: 1.5497x; 1.5255x over previous
#include <cuda_runtime.h>

#define IW 512
#define H 256
#define OW 512
#define E 64
#define NA 2048
#define NAP 2560
#define XP 2560           // column stride of g_vd
#define CH 32             // token chunk per worklist entry
#define MAXWL 128

typedef unsigned long long u64;

// ---------------- device scratch (no allocs allowed) ----------------
__device__ __align__(16) u64   g_vd[(size_t)H * XP];   // 5.2 MB (relu v, relu v) dup [h][perm]
__device__ int   g_topk_idx[NA];
__device__ float g_topk_score[NA];
__device__ int   g_seg_start[E + 1];
__device__ int   g_seg_cnt[E];
__device__ int   g_perm_a[NAP];
__device__ float g_perm_score[NAP];
__device__ int   g_wl[MAXWL];      // (expert<<16) | chunk_start
__device__ int   g_wl_n;

// ---------------- packed f32x2 helpers (sm_103a) ----------------
__device__ __forceinline__ u64 pack2(float a, float b) {
    u64 r; unsigned ai = __float_as_uint(a), bi = __float_as_uint(b);
    asm("mov.b64 %0, {%1, %2};" : "=l"(r) : "r"(ai), "r"(bi));
    return r;
}
__device__ __forceinline__ void ffma2(u64 &d, u64 a, u64 b) {
    asm("fma.rn.f32x2 %0, %1, %2, %0;" : "+l"(d) : "l"(a), "l"(b));
}
__device__ __forceinline__ float2 unpack2(u64 v) {
    unsigned lo, hi;
    asm("mov.b64 {%0, %1}, %2;" : "=r"(lo), "=r"(hi) : "l"(v));
    float2 f; f.x = __uint_as_float(lo); f.y = __uint_as_float(hi);
    return f;
}

// ---------------- kernel 1: routing (+ fused d_out zeroing) ----------------
__global__ __launch_bounds__(256) void routing_kernel(
    const float* __restrict__ x, const float* __restrict__ noise,
    const float* __restrict__ mixer, const float* __restrict__ nctl,
    float4* __restrict__ out)
{
    __shared__ __align__(16) u64 mns[32][64];
    __shared__ __align__(16) u64 xs2[8][32];
    __shared__ float hs[8][64];
    int tid = threadIdx.x;
    int t0 = blockIdx.x * 8;
    int ee = tid & 63, tg = tid >> 6;

    {   // fused zero of d_out: 131072 float4 over 32768 threads
        int base = blockIdx.x * 256 + tid;
        float4 z = make_float4(0.f, 0.f, 0.f, 0.f);
#pragma unroll
        for (int q = 0; q < 4; q++) out[base + q * 32768] = z;
    }

    u64 acc2[2] = {0ull, 0ull};

    for (int i0 = 0; i0 < IW; i0 += 32) {
#pragma unroll
        for (int q = 0; q < 8; q++) {
            int id = tid + 256 * q; int ii = id >> 6, e2 = id & 63;
            mns[ii][e2] = pack2(mixer[(i0 + ii) * E + e2], nctl[(i0 + ii) * E + e2]);
        }
        {
            int tt = tid >> 5, ii = tid & 31;
            if (tt < 8) {
                float v = x[(t0 + tt) * IW + i0 + ii];
                xs2[tt][ii] = pack2(v, v);
            }
        }
        __syncthreads();
#pragma unroll 8
        for (int ii = 0; ii < 32; ii++) {
            u64 mn = mns[ii][ee];
            ffma2(acc2[0], xs2[tg * 2 + 0][ii], mn);
            ffma2(acc2[1], xs2[tg * 2 + 1][ii], mn);
        }
        __syncthreads();
    }

#pragma unroll
    for (int j = 0; j < 2; j++) {
        int t = tg * 2 + j;
        float2 a = unpack2(acc2[j]);
        float z = a.y;
        float sp = (z > 20.f) ? z : log1pf(expf(z));
        hs[t][ee] = a.x + noise[(t0 + t) * E + ee] * sp;
    }
    __syncthreads();

    if (tid < 8) {
        int t = tid;
        float v0 = -1e30f, v1 = -1e30f; int i0 = -1, i1 = -1;
        for (int ec = 0; ec < 64; ec++) {
            float v = hs[t][ec];
            if (v > v0)      { v1 = v0; i1 = i0; v0 = v; i0 = ec; }
            else if (v > v1) { v1 = v; i1 = ec; }
        }
        float e1 = expf(v1 - v0);
        float s0 = 1.f / (1.f + e1);
        float s1 = e1 * s0;
        g_topk_idx[(t0 + t) * 2 + 0] = i0;
        g_topk_idx[(t0 + t) * 2 + 1] = i1;
        g_topk_score[(t0 + t) * 2 + 0] = s0;
        g_topk_score[(t0 + t) * 2 + 1] = s1;
    }
}

// ---------------- kernel 2: group + deterministic worklist ----------------
__global__ __launch_bounds__(256) void group_kernel()
{
    __shared__ int cnt[E];
    __shared__ int st[E + 1];
    __shared__ int cur[E];
    __shared__ int wo[E];
    int tid = threadIdx.x;
    if (tid < E) cnt[tid] = 0;
    __syncthreads();
    for (int a = tid; a < NA; a += 256) atomicAdd(&cnt[g_topk_idx[a]], 1);
    __syncthreads();
    if (tid == 0) {
        int run = 0, wrun = 0;
        for (int e2 = 0; e2 < E; e2++) {
            st[e2] = run;
            run = (run + cnt[e2] + 7) & ~7;      // 8-aligned segment starts
            wo[e2] = wrun;
            wrun += (cnt[e2] + CH - 1) / CH;
        }
        st[E] = run;
        g_wl_n = wrun;
    }
    __syncthreads();
    if (tid < E) { cur[tid] = st[tid]; g_seg_cnt[tid] = cnt[tid]; }
    if (tid <= E) g_seg_start[tid] = st[tid];
    __syncthreads();
    for (int a = tid; a < NA; a += 256) {
        int e2 = g_topk_idx[a];
        int pos = atomicAdd(&cur[e2], 1);
        g_perm_a[pos] = a;
        g_perm_score[pos] = g_topk_score[a];
    }
    __syncthreads();
    if (tid < E) {
        for (int p = st[tid] + cnt[tid]; p < st[tid + 1]; p++) {
            g_perm_a[p] = 0; g_perm_score[p] = 0.f;
        }
        for (int c = 0; c * CH < cnt[tid]; c++)
            g_wl[wo[tid] + c] = (tid << 16) | (c * CH);
    }
    for (int p = st[E] + tid; p < NAP; p += 256) {
        g_perm_a[p] = 0; g_perm_score[p] = 0.f;
    }
}

// ---------------- kernel 3: ffn1 -> relu'd dup transpose into g_vd --------
// grid (MAXWL, 2 hc), 128 thr. Warp = 8 tok x 128 h (4 h/lane).
// per kk: 1 LDS.128 (W) + 4 broadcast LDS.128 (x-dup) + 16 FFMA2.
__global__ __launch_bounds__(128) void ffn1_kernel(
    const float* __restrict__ w1s, const float* __restrict__ b1s,
    const float* __restrict__ x)
{
    __shared__ __align__(16) float ws[32][132];  // 16.9 KB
    __shared__ __align__(16) u64 xd[32][34];     // [k][tok] dup, 8.7 KB
    __shared__ int tok[32];
    int bx = blockIdx.x;
    if (bx >= g_wl_n) return;
    int ent = g_wl[bx];
    int e = ent >> 16, c0 = ent & 0xffff;
    int hc = blockIdx.y;
    int s = g_seg_start[e];
    int nt = min(CH, g_seg_cnt[e] - c0);
    int tid = threadIdx.x, w = tid >> 5, l = tid & 31;
    const float* wbase = w1s + (size_t)e * IW * H + hc * 128;

    int wr[8], wc[8];
#pragma unroll
    for (int q = 0; q < 8; q++) {
        int f4 = tid + 128 * q;
        wr[q] = f4 >> 5; wc[q] = (f4 & 31) * 4;
    }
    int xk = tid & 31;                 // k-row within tile for x fill
    int xtt[8];                        // token index per fill pass
#pragma unroll
    for (int q = 0; q < 8; q++) xtt[q] = (tid >> 5) + 4 * q;

    if (tid < 32) tok[tid] = (tid < nt) ? (g_perm_a[s + c0 + tid] >> 1) : -1;
    __syncthreads();
    int tki[8];
#pragma unroll
    for (int q = 0; q < 8; q++) tki[q] = tok[xtt[q]];

    // prologue prefetch: tile i0 = 0
    float4 pw[8]; float px[8];
#pragma unroll
    for (int q = 0; q < 8; q++)
        pw[q] = *(const float4*)(wbase + (size_t)wr[q] * H + wc[q]);
#pragma unroll
    for (int q = 0; q < 8; q++)
        px[q] = (tki[q] >= 0) ? x[tki[q] * IW + xk] : 0.f;

    u64 acc[8][2];
    float4 bv = *(const float4*)(b1s + e * H + hc * 128 + l * 4);
#pragma unroll
    for (int j = 0; j < 8; j++) {
        acc[j][0] = pack2(bv.x, bv.y);
        acc[j][1] = pack2(bv.z, bv.w);
    }

    for (int i0 = 0; i0 < IW; i0 += 32) {
#pragma unroll
        for (int q = 0; q < 8; q++)
            *(float4*)&ws[wr[q]][wc[q]] = pw[q];
#pragma unroll
        for (int q = 0; q < 8; q++)
            xd[xk][xtt[q]] = pack2(px[q], px[q]);
        __syncthreads();

        if (i0 + 32 < IW) {
            const float* wb = wbase + (size_t)(i0 + 32) * H;
#pragma unroll
            for (int q = 0; q < 8; q++)
                pw[q] = *(const float4*)(wb + (size_t)wr[q] * H + wc[q]);
#pragma unroll
            for (int q = 0; q < 8; q++)
                px[q] = (tki[q] >= 0) ? x[tki[q] * IW + i0 + 32 + xk] : 0.f;
        }
#pragma unroll 4
        for (int kk = 0; kk < 32; kk++) {
            ulonglong2 wl2 = *(ulonglong2*)&ws[kk][l * 4];
            ulonglong2 xa = *(ulonglong2*)&xd[kk][w * 8];
            ulonglong2 xb = *(ulonglong2*)&xd[kk][w * 8 + 2];
            ulonglong2 xc = *(ulonglong2*)&xd[kk][w * 8 + 4];
            ulonglong2 xe = *(ulonglong2*)&xd[kk][w * 8 + 6];
            ffma2(acc[0][0], xa.x, wl2.x); ffma2(acc[0][1], xa.x, wl2.y);
            ffma2(acc[1][0], xa.y, wl2.x); ffma2(acc[1][1], xa.y, wl2.y);
            ffma2(acc[2][0], xb.x, wl2.x); ffma2(acc[2][1], xb.x, wl2.y);
            ffma2(acc[3][0], xb.y, wl2.x); ffma2(acc[3][1], xb.y, wl2.y);
            ffma2(acc[4][0], xc.x, wl2.x); ffma2(acc[4][1], xc.x, wl2.y);
            ffma2(acc[5][0], xc.y, wl2.x); ffma2(acc[5][1], xc.y, wl2.y);
            ffma2(acc[6][0], xe.x, wl2.x); ffma2(acc[6][1], xe.x, wl2.y);
            ffma2(acc[7][0], xe.y, wl2.x); ffma2(acc[7][1], xe.y, wl2.y);
        }
        __syncthreads();
    }

    // epilogue: relu + transposed dup write g_vd[h][perm]
    float r[8][4];
#pragma unroll
    for (int j = 0; j < 8; j++) {
        float2 f0 = unpack2(acc[j][0]), f1 = unpack2(acc[j][1]);
        r[j][0] = fmaxf(f0.x, 0.f); r[j][1] = fmaxf(f0.y, 0.f);
        r[j][2] = fmaxf(f1.x, 0.f); r[j][3] = fmaxf(f1.y, 0.f);
    }
    int hbase = hc * 128 + l * 4;
    int pbase = s + c0 + w * 8;
    int rem = nt - w * 8;
    if (rem >= 8) {
#pragma unroll
        for (int hh = 0; hh < 4; hh++) {
            u64* dst = g_vd + (size_t)(hbase + hh) * XP + pbase;
            ulonglong2 v0, v1, v2, v3;
            v0.x = pack2(r[0][hh], r[0][hh]); v0.y = pack2(r[1][hh], r[1][hh]);
            v1.x = pack2(r[2][hh], r[2][hh]); v1.y = pack2(r[3][hh], r[3][hh]);
            v2.x = pack2(r[4][hh], r[4][hh]); v2.y = pack2(r[5][hh], r[5][hh]);
            v3.x = pack2(r[6][hh], r[6][hh]); v3.y = pack2(r[7][hh], r[7][hh]);
            *(ulonglong2*)(dst + 0) = v0;
            *(ulonglong2*)(dst + 2) = v1;
            *(ulonglong2*)(dst + 4) = v2;
            *(ulonglong2*)(dst + 6) = v3;
        }
    } else if (rem > 0) {
        for (int j = 0; j < rem; j++)
#pragma unroll
            for (int hh = 0; hh < 4; hh++)
                g_vd[(size_t)(hbase + hh) * XP + pbase + j] = pack2(r[j][hh], r[j][hh]);
    }
}

// ---------------- kernel 4: ffn2: out += score * (relu(V) @ W2 + b2) --------
// grid (MAXWL, 4 oc), 128 thr. Warp = 8 tok x 128 o. V-dup tiles copied from
// g_vd into smem (plain coalesced copy), broadcast LDS in mainloop. Atomic
// epilogue: exactly 2 commutative fp adds per out element -> deterministic.
__global__ __launch_bounds__(128) void ffn2_kernel(
    const float* __restrict__ w2s, const float* __restrict__ b2s,
    float* __restrict__ out)
{
    __shared__ __align__(16) float ws2[32][132];
    __shared__ __align__(16) u64 vd2[32][34];
    int bx = blockIdx.x;
    if (bx >= g_wl_n) return;
    int ent = g_wl[bx];
    int e = ent >> 16, c0 = ent & 0xffff;
    int oc = blockIdx.y;
    int s = g_seg_start[e];
    int nt = min(CH, g_seg_cnt[e] - c0);
    int tid = threadIdx.x, w = tid >> 5, l = tid & 31;
    const float* wbase = w2s + (size_t)e * H * OW + oc * 128;
    int pbase0 = s + c0;

    int wr[8], wc[8];
#pragma unroll
    for (int q = 0; q < 8; q++) {
        int f4 = tid + 128 * q;
        wr[q] = f4 >> 5; wc[q] = (f4 & 31) * 4;
    }
    int vhh[4], vcc[4];
#pragma unroll
    for (int q = 0; q < 4; q++) {
        int id = tid + 128 * q;                  // 512 ulonglong2
        vhh[q] = id >> 4; vcc[q] = (id & 15) * 2;
    }

    // prologue prefetch: tile h0 = 0
    float4 pw[8]; ulonglong2 pv[4];
#pragma unroll
    for (int q = 0; q < 8; q++)
        pw[q] = *(const float4*)(wbase + (size_t)wr[q] * OW + wc[q]);
#pragma unroll
    for (int q = 0; q < 4; q++)
        pv[q] = *(const ulonglong2*)(g_vd + (size_t)vhh[q] * XP + pbase0 + vcc[q]);

    u64 acc[8][2];
    float4 bv = *(const float4*)(b2s + e * OW + oc * 128 + l * 4);
#pragma unroll
    for (int j = 0; j < 8; j++) {
        acc[j][0] = pack2(bv.x, bv.y);
        acc[j][1] = pack2(bv.z, bv.w);
    }

    for (int h0 = 0; h0 < H; h0 += 32) {
#pragma unroll
        for (int q = 0; q < 8; q++)
            *(float4*)&ws2[wr[q]][wc[q]] = pw[q];
#pragma unroll
        for (int q = 0; q < 4; q++)
            *(ulonglong2*)&vd2[vhh[q]][vcc[q]] = pv[q];
        __syncthreads();

        if (h0 + 32 < H) {
            const float* wb = wbase + (size_t)(h0 + 32) * OW;
#pragma unroll
            for (int q = 0; q < 8; q++)
                pw[q] = *(const float4*)(wb + (size_t)wr[q] * OW + wc[q]);
#pragma unroll
            for (int q = 0; q < 4; q++)
                pv[q] = *(const ulonglong2*)(g_vd +
                    (size_t)(h0 + 32 + vhh[q]) * XP + pbase0 + vcc[q]);
        }
#pragma unroll 4
        for (int kk = 0; kk < 32; kk++) {
            ulonglong2 wl2 = *(ulonglong2*)&ws2[kk][l * 4];
            ulonglong2 va = *(ulonglong2*)&vd2[kk][w * 8];
            ulonglong2 vb = *(ulonglong2*)&vd2[kk][w * 8 + 2];
            ulonglong2 vc = *(ulonglong2*)&vd2[kk][w * 8 + 4];
            ulonglong2 ve = *(ulonglong2*)&vd2[kk][w * 8 + 6];
            ffma2(acc[0][0], va.x, wl2.x); ffma2(acc[0][1], va.x, wl2.y);
            ffma2(acc[1][0], va.y, wl2.x); ffma2(acc[1][1], va.y, wl2.y);
            ffma2(acc[2][0], vb.x, wl2.x); ffma2(acc[2][1], vb.x, wl2.y);
            ffma2(acc[3][0], vb.y, wl2.x); ffma2(acc[3][1], vb.y, wl2.y);
            ffma2(acc[4][0], vc.x, wl2.x); ffma2(acc[4][1], vc.x, wl2.y);
            ffma2(acc[5][0], vc.y, wl2.x); ffma2(acc[5][1], vc.y, wl2.y);
            ffma2(acc[6][0], ve.x, wl2.x); ffma2(acc[6][1], ve.x, wl2.y);
            ffma2(acc[7][0], ve.y, wl2.x); ffma2(acc[7][1], ve.y, wl2.y);
        }
        __syncthreads();
    }

#pragma unroll
    for (int j = 0; j < 8; j++) {
        int t = w * 8 + j;
        if (t < nt) {
            int   a  = g_perm_a[s + c0 + t];
            float sc = g_perm_score[s + c0 + t];
            int   tk = a >> 1;
            float* dst = out + (size_t)tk * OW + oc * 128 + l * 4;
            float2 f0 = unpack2(acc[j][0]), f1 = unpack2(acc[j][1]);
            atomicAdd(dst + 0, sc * f0.x);
            atomicAdd(dst + 1, sc * f0.y);
            atomicAdd(dst + 2, sc * f1.x);
            atomicAdd(dst + 3, sc * f1.y);
        }
    }
}

// ---------------- launcher ----------------
extern "C" void kernel_launch(void* const* d_in, const int* in_sizes, int n_in,
                              void* d_out, int out_size)
{
    const float* x     = (const float*)d_in[0];
    const float* noise = (const float*)d_in[1];
    const float* w1s   = (const float*)d_in[2];
    const float* b1s   = (const float*)d_in[3];
    const float* w2s   = (const float*)d_in[4];
    const float* b2s   = (const float*)d_in[5];
    const float* mixer = (const float*)d_in[6];
    const float* nctl  = (const float*)d_in[7];

    routing_kernel<<<128, 256>>>(x, noise, mixer, nctl, (float4*)d_out);
    group_kernel<<<1, 256>>>();
    ffn1_kernel<<<dim3(MAXWL, 2), 128>>>(w1s, b1s, x);
    ffn2_kernel<<<dim3(MAXWL, 4), 128>>>(w2s, b2s, (float*)d_out);
}